// round 6
// baseline (speedup 1.0000x reference)
#include <cuda_runtime.h>
#include <cuda_bf16.h>
#include <stdint.h>

#define HH 16
#define SS 4096
#define DD 64

__device__ __align__(16) __nv_bfloat16 g_qhi[HH * SS * DD];
__device__ __align__(16) __nv_bfloat16 g_qlo[HH * SS * DD];
__device__ __align__(16) __nv_bfloat16 g_khi[HH * SS * DD];
__device__ __align__(16) __nv_bfloat16 g_klo[HH * SS * DD];
__device__ __align__(16) __nv_bfloat16 g_vthi[HH * DD * SS];
__device__ __align__(16) __nv_bfloat16 g_vtlo[HH * DD * SS];
__device__ __align__(16) unsigned char g_mask8[(size_t)SS * SS];
__device__ __align__(16) uint32_t g_pp[(size_t)HH * SS * SS];   // packed bf16 hi|lo of exp(s)
__device__ float g_se[(size_t)HH * 64 * SS];                    // per-64col-strip row sums
__device__ float g_rowinv[HH * SS];

static __device__ __forceinline__ uint32_t smem_u32(const void* p) {
    uint32_t a;
    asm("{ .reg .u64 t; cvta.to.shared.u64 t, %1; cvt.u32.u64 %0, t; }" : "=r"(a) : "l"(p));
    return a;
}
static __device__ __forceinline__ void ldsm4(uint32_t* r, uint32_t a) {
    asm volatile("ldmatrix.sync.aligned.m8n8.x4.shared.b16 {%0,%1,%2,%3}, [%4];"
        : "=r"(r[0]), "=r"(r[1]), "=r"(r[2]), "=r"(r[3]) : "r"(a));
}
static __device__ __forceinline__ void mma16816(float* c, const uint32_t* a,
                                                uint32_t b0, uint32_t b1) {
    asm volatile("mma.sync.aligned.m16n8k16.row.col.f32.bf16.bf16.f32 "
        "{%0,%1,%2,%3}, {%4,%5,%6,%7}, {%8,%9}, {%0,%1,%2,%3};"
        : "+f"(c[0]), "+f"(c[1]), "+f"(c[2]), "+f"(c[3])
        : "r"(a[0]), "r"(a[1]), "r"(a[2]), "r"(a[3]), "r"(b0), "r"(b1));
}
static __device__ __forceinline__ uint32_t packsplit(float e) {
    __nv_bfloat16 hb = __float2bfloat16(e);
    float hf = __bfloat162float(hb);
    __nv_bfloat16 lb = __float2bfloat16(e - hf);
    return ((uint32_t)__bfloat16_as_ushort(hb) << 16) | (uint32_t)__bfloat16_as_ushort(lb);
}

// ===================== converts =====================
__global__ __launch_bounds__(256) void convert_qk(const float* __restrict__ q,
                                                  const float* __restrict__ k) {
    int i = blockIdx.x * 256 + threadIdx.x;
    float fq = q[i] * 0.125f;
    __nv_bfloat16 qh = __float2bfloat16(fq);
    g_qhi[i] = qh; g_qlo[i] = __float2bfloat16(fq - __bfloat162float(qh));
    float fk = k[i];
    __nv_bfloat16 kh = __float2bfloat16(fk);
    g_khi[i] = kh; g_klo[i] = __float2bfloat16(fk - __bfloat162float(kh));
}
__global__ __launch_bounds__(256) void convert_v(const float* __restrict__ v) {
    __shared__ __nv_bfloat16 th[64][65], tl[64][65];
    const int h = blockIdx.y, s0 = blockIdx.x * 64, tid = threadIdx.x;
#pragma unroll
    for (int j = 0; j < 16; j++) {
        int i = tid + j * 256, sr = i >> 6, d = i & 63;
        float f = v[((size_t)(h * SS + s0 + sr)) * DD + d];
        __nv_bfloat16 hi = __float2bfloat16(f);
        th[sr][d] = hi; tl[sr][d] = __float2bfloat16(f - __bfloat162float(hi));
    }
    __syncthreads();
#pragma unroll
    for (int j = 0; j < 16; j++) {
        int i = tid + j * 256, d = i >> 6, sr = i & 63;
        size_t o = ((size_t)(h * DD + d)) * SS + s0 + sr;
        g_vthi[o] = th[sr][d]; g_vtlo[o] = tl[sr][d];
    }
}
__global__ __launch_bounds__(256) void convert_mask(const int* __restrict__ m) {
    size_t i = ((size_t)blockIdx.x * 256 + threadIdx.x) * 4;
    int4 v = *(const int4*)(m + i);
    uchar4 b;
    b.x = v.x ? 1 : 0; b.y = v.y ? 1 : 0; b.z = v.z ? 1 : 0; b.w = v.w ? 1 : 0;
    *(uchar4*)(g_mask8 + i) = b;
}

// ===================== K1: scores + exp + split + strip sums =====================
#define K1_QHI 0
#define K1_QLO 18432
#define K1_KHI 36864
#define K1_KLO 55296
#define K1_MSK 73728
#define K1_BYTES (K1_MSK + 128 * 144)

__global__ __launch_bounds__(256) void scores_mma() {
    extern __shared__ char sm[];
    const uint32_t sb = smem_u32(sm);
    const int h = blockIdx.x, q0 = blockIdx.y * 128, tid = threadIdx.x;
    const int wid = tid >> 5, lane = tid & 31;

    {   // Q tile (128 x 64), hi+lo
        const __nv_bfloat16* qh = g_qhi + ((size_t)(h * SS + q0)) * DD;
        const __nv_bfloat16* ql = g_qlo + ((size_t)(h * SS + q0)) * DD;
#pragma unroll
        for (int j = 0; j < 4; j++) {
            int i = tid + j * 256, row = i >> 3, u = i & 7;
            *(uint4*)(sm + K1_QHI + row * 144 + u * 16) = *(const uint4*)(qh + row * DD + u * 8);
            *(uint4*)(sm + K1_QLO + row * 144 + u * 16) = *(const uint4*)(ql + row * DD + u * 8);
        }
    }
    const int warp_m = wid & 3, warp_n = wid >> 2;
    const int lr = lane & 15, lc = lane >> 4;
    const uint32_t aoff = sb + K1_QHI + (uint32_t)(warp_m * 32 + lr) * 144 + lc * 16;
    const uint32_t boff = sb + K1_KHI + (uint32_t)(warp_n * 64 + lr) * 144 + lc * 16;

    for (int kt = 0; kt < 32; kt++) {
        {   // K tile + mask bytes
            const __nv_bfloat16* kh = g_khi + ((size_t)(h * SS + kt * 128)) * DD;
            const __nv_bfloat16* kl = g_klo + ((size_t)(h * SS + kt * 128)) * DD;
#pragma unroll
            for (int j = 0; j < 4; j++) {
                int i = tid + j * 256, row = i >> 3, u = i & 7;
                *(uint4*)(sm + K1_KHI + row * 144 + u * 16) = *(const uint4*)(kh + row * DD + u * 8);
                *(uint4*)(sm + K1_KLO + row * 144 + u * 16) = *(const uint4*)(kl + row * DD + u * 8);
            }
#pragma unroll
            for (int j = 0; j < 4; j++) {  // 1024 uint4 of mask bytes
                int i = tid + j * 256, row = i >> 3, u = i & 7;
                *(uint4*)(sm + K1_MSK + row * 144 + u * 16) =
                    *(const uint4*)(g_mask8 + (size_t)(q0 + row) * SS + kt * 128 + u * 16);
            }
        }
        __syncthreads();

        float acc[2][8][4];
#pragma unroll
        for (int mi = 0; mi < 2; mi++)
#pragma unroll
            for (int n = 0; n < 8; n++)
#pragma unroll
                for (int c = 0; c < 4; c++) acc[mi][n][c] = 0.f;

#pragma unroll
        for (int ks = 0; ks < 4; ks++) {
            uint32_t ah[2][4], al[2][4];
            ldsm4(ah[0], aoff + ks * 32);
            ldsm4(ah[1], aoff + ks * 32 + 16 * 144);
            ldsm4(al[0], aoff + 18432 + ks * 32);
            ldsm4(al[1], aoff + 18432 + ks * 32 + 16 * 144);
#pragma unroll
            for (int ng = 0; ng < 4; ng++) {
                uint32_t bh[4], bl[4];
                ldsm4(bh, boff + ks * 32 + ng * 16 * 144);
                ldsm4(bl, boff + 18432 + ks * 32 + ng * 16 * 144);
#pragma unroll
                for (int mi = 0; mi < 2; mi++) {
                    mma16816(acc[mi][2 * ng], ah[mi], bh[0], bh[2]);
                    mma16816(acc[mi][2 * ng + 1], ah[mi], bh[1], bh[3]);
                    mma16816(acc[mi][2 * ng], ah[mi], bl[0], bl[2]);
                    mma16816(acc[mi][2 * ng + 1], ah[mi], bl[1], bl[3]);
                    mma16816(acc[mi][2 * ng], al[mi], bh[0], bh[2]);
                    mma16816(acc[mi][2 * ng + 1], al[mi], bh[1], bh[3]);
                }
            }
        }
        // epilogue: mask -> exp -> split/store + strip sums
        const unsigned char* mp = (const unsigned char*)(sm + K1_MSK);
#pragma unroll
        for (int mi = 0; mi < 2; mi++) {
            int rowl = warp_m * 32 + mi * 16 + (lane >> 2);
            float sA = 0.f, sB = 0.f;
#pragma unroll
            for (int ng = 0; ng < 8; ng++) {
                int coll = warp_n * 64 + ng * 8 + (lane & 3) * 2;
                uchar2 m0 = *(const uchar2*)(mp + rowl * 144 + coll);
                uchar2 m1 = *(const uchar2*)(mp + (rowl + 8) * 144 + coll);
                float e0 = m0.x ? 0.f : __expf(acc[mi][ng][0]);
                float e1 = m0.y ? 0.f : __expf(acc[mi][ng][1]);
                float e2 = m1.x ? 0.f : __expf(acc[mi][ng][2]);
                float e3 = m1.y ? 0.f : __expf(acc[mi][ng][3]);
                sA += e0 + e1; sB += e2 + e3;
                size_t base = ((size_t)(h * SS + q0 + rowl)) * SS + kt * 128 + coll;
                *(uint2*)(g_pp + base) = make_uint2(packsplit(e0), packsplit(e1));
                *(uint2*)(g_pp + base + 8 * SS) = make_uint2(packsplit(e2), packsplit(e3));
            }
            sA += __shfl_xor_sync(~0u, sA, 1); sA += __shfl_xor_sync(~0u, sA, 2);
            sB += __shfl_xor_sync(~0u, sB, 1); sB += __shfl_xor_sync(~0u, sB, 2);
            if ((lane & 3) == 0) {
                size_t so = ((size_t)(h * 64 + kt * 2 + warp_n)) * SS + q0;
                g_se[so + rowl] = sA; g_se[so + rowl + 8] = sB;
            }
        }
        __syncthreads();
    }
}

// ===================== K2: row inverse sums =====================
__global__ __launch_bounds__(256) void rowinv_kernel() {
    int idx = blockIdx.x * 256 + threadIdx.x;
    int h = idx >> 12, row = idx & 4095;
    float s = 0.f;
#pragma unroll 8
    for (int t = 0; t < 64; t++) s += g_se[((size_t)(h * 64 + t)) * SS + row];
    g_rowinv[idx] = 1.0f / s;
}

// ===================== K3: normalize + attn write + PV =====================
#define K3_PHI 0
#define K3_PLO 34816
#define K3_VHI 69632
#define K3_VLO 87040
#define K3_ROWI 104448
#define K3_BYTES (K3_ROWI + 512)

__global__ __launch_bounds__(256) void pv_mma(float* __restrict__ attn,
                                              float* __restrict__ out) {
    extern __shared__ char sm[];
    const uint32_t sb = smem_u32(sm);
    const int h = blockIdx.x, q0 = blockIdx.y * 128, tid = threadIdx.x;
    const int wid = tid >> 5, lane = tid & 31;
    const int lr = lane & 15, lc = lane >> 4;
    float* rowi = (float*)(sm + K3_ROWI);

    if (tid < 128) rowi[tid] = g_rowinv[h * SS + q0 + tid];
    __syncthreads();

    float acc[8][4];
#pragma unroll
    for (int n = 0; n < 8; n++)
#pragma unroll
        for (int c = 0; c < 4; c++) acc[n][c] = 0.f;

    const uint32_t aoff = sb + K3_PHI + (uint32_t)(wid * 16 + lr) * 272 + lc * 16;
    const uint32_t boff = sb + K3_VHI + (uint32_t)lr * 272 + lc * 16;

    for (int kt = 0; kt < 32; kt++) {
        const int k0 = kt * 128;
#pragma unroll
        for (int j = 0; j < 16; j++) {  // stage P (unpack) + write final attn
            int i = tid + j * 256, row = i >> 5, c4 = i & 31;
            size_t base = ((size_t)(h * SS + q0 + row)) * SS + k0 + c4 * 4;
            uint4 pp = *(const uint4*)(g_pp + base);
            uint32_t h0, l0, h1, l1;
            asm("prmt.b32 %0, %1, %2, 0x7632;" : "=r"(h0) : "r"(pp.x), "r"(pp.y));
            asm("prmt.b32 %0, %1, %2, 0x5410;" : "=r"(l0) : "r"(pp.x), "r"(pp.y));
            asm("prmt.b32 %0, %1, %2, 0x7632;" : "=r"(h1) : "r"(pp.z), "r"(pp.w));
            asm("prmt.b32 %0, %1, %2, 0x5410;" : "=r"(l1) : "r"(pp.z), "r"(pp.w));
            *(uint2*)(sm + K3_PHI + row * 272 + c4 * 8) = make_uint2(h0, h1);
            *(uint2*)(sm + K3_PLO + row * 272 + c4 * 8) = make_uint2(l0, l1);
            float ri = rowi[row];
            float4 a;
            a.x = (__uint_as_float(pp.x & 0xffff0000u) + __uint_as_float(pp.x << 16)) * ri;
            a.y = (__uint_as_float(pp.y & 0xffff0000u) + __uint_as_float(pp.y << 16)) * ri;
            a.z = (__uint_as_float(pp.z & 0xffff0000u) + __uint_as_float(pp.z << 16)) * ri;
            a.w = (__uint_as_float(pp.w & 0xffff0000u) + __uint_as_float(pp.w << 16)) * ri;
            *(float4*)(attn + base) = a;
        }
#pragma unroll
        for (int j = 0; j < 4; j++) {  // V tiles [64 d][128 k]
            int i = tid + j * 256, d = i >> 4, u = i & 15;
            size_t go = ((size_t)(h * DD + d)) * SS + k0 + u * 8;
            *(uint4*)(sm + K3_VHI + d * 272 + u * 16) = *(const uint4*)(g_vthi + go);
            *(uint4*)(sm + K3_VLO + d * 272 + u * 16) = *(const uint4*)(g_vtlo + go);
        }
        __syncthreads();

#pragma unroll
        for (int ks = 0; ks < 8; ks++) {
            uint32_t ah[4], al[4];
            ldsm4(ah, aoff + ks * 32);
            ldsm4(al, aoff + K3_PLO + ks * 32);
#pragma unroll
            for (int ng = 0; ng < 4; ng++) {
                uint32_t bh[4], bl[4];
                ldsm4(bh, boff + ks * 32 + ng * 16 * 272);
                ldsm4(bl, boff + 17408 + ks * 32 + ng * 16 * 272);
                mma16816(acc[2 * ng], ah, bh[0], bh[2]);
                mma16816(acc[2 * ng + 1], ah, bh[1], bh[3]);
                mma16816(acc[2 * ng], ah, bl[0], bl[2]);
                mma16816(acc[2 * ng + 1], ah, bl[1], bl[3]);
                mma16816(acc[2 * ng], al, bh[0], bh[2]);
                mma16816(acc[2 * ng + 1], al, bh[1], bh[3]);
            }
        }
        __syncthreads();
    }
    const int rowl = wid * 16 + (lane >> 2);
    const float riA = rowi[rowl], riB = rowi[rowl + 8];
#pragma unroll
    for (int ng = 0; ng < 8; ng++) {
        int col = ng * 8 + (lane & 3) * 2;
        float* op = out + ((size_t)(h * SS + q0 + rowl)) * DD + col;
        *(float2*)op = make_float2(acc[ng][0] * riA, acc[ng][1] * riA);
        *(float2*)(op + 8 * DD) = make_float2(acc[ng][2] * riB, acc[ng][3] * riB);
    }
}

// ===================== launch =====================
extern "C" void kernel_launch(void* const* d_in, const int* in_sizes, int n_in,
                              void* d_out, int out_size) {
    const float* q = (const float*)d_in[0];
    const float* k = (const float*)d_in[1];
    const float* v = (const float*)d_in[2];
    const int* mask = (const int*)d_in[3];
    float* out = (float*)d_out;
    float* attn = out + (size_t)HH * SS * DD;

    cudaFuncSetAttribute(scores_mma, cudaFuncAttributeMaxDynamicSharedMemorySize, K1_BYTES);
    cudaFuncSetAttribute(pv_mma, cudaFuncAttributeMaxDynamicSharedMemorySize, K3_BYTES);

    convert_qk<<<(HH * SS * DD) / 256, 256>>>(q, k);
    convert_v<<<dim3(SS / 64, HH), 256>>>(v);
    convert_mask<<<(SS * SS) / 1024, 256>>>(mask);
    scores_mma<<<dim3(HH, SS / 128), 256, K1_BYTES>>>();
    rowinv_kernel<<<HH * SS / 256, 256>>>();
    pv_mma<<<dim3(HH, SS / 128), 256, K3_BYTES>>>(attn, out);
}